// round 10
// baseline (speedup 1.0000x reference)
#include <cuda_runtime.h>
#include <cstdint>

#define NXg   240
#define NPAD  256
#define CN    16     // cluster size (CTAs)
#define RPC   15     // rows per CTA
#define RPAD  16     // padded row count (row 15 zero)
#define NTH   256    // 8 warps
#define NW    8
#define FFACf 0.4f
#define OMFf  0.6f

typedef unsigned long long ull;

struct __align__(16) Smem {
    alignas(16) ull   mbar[2];            // ping-pong cluster barriers (count=16)
    alignas(16) float scal[12];           // 9 global scalars (per-CTA replicated)
    alignas(16) float udirs[16];
    alignas(16) float wred2[NW][2];
    alignas(16) float redF[CN][2];        // final-energy cluster slots
    alignas(16) float uho [NPAD];
    alignas(16) float wbuf [2][2][NPAD];  // ping-pong wavefunctions (local)
    alignas(16) float fball[2][2][NPAD];  // ping-pong broadcast fb vectors (DSMEM-filled)
    alignas(16) float kin [RPAD][NPAD];
    alignas(16) float vint[RPAD][NPAD];
};

__device__ __forceinline__ uint32_t smem_u32(const void* p) {
    return (uint32_t)__cvta_generic_to_shared(p);
}
__device__ __forceinline__ uint32_t mapa_u32(uint32_t laddr, int rank) {
    uint32_t r;
    asm("mapa.shared::cluster.u32 %0, %1, %2;" : "=r"(r) : "r"(laddr), "r"(rank));
    return r;
}
__device__ __forceinline__ void st_remote_f32(uint32_t raddr, float v) {
    asm volatile("st.shared::cluster.u32 [%0], %1;" :: "r"(raddr), "r"(__float_as_uint(v)) : "memory");
}
__device__ __forceinline__ void st_cluster_f32(uint32_t laddr, int rank, float v) {
    st_remote_f32(mapa_u32(laddr, rank), v);
}
__device__ __forceinline__ void mbar_arrive_remote(uint32_t laddr, int rank) {
    asm volatile("{\n\t.reg .b32 ra;\n\t"
        "mapa.shared::cluster.u32 ra, %0, %1;\n\t"
        "mbarrier.arrive.release.cluster.shared::cluster.b64 _, [ra];\n\t}"
        :: "r"(laddr), "r"(rank) : "memory");
}
__device__ __forceinline__ void mbar_wait_parity(uint32_t addr, uint32_t parity) {
    uint32_t done;
    asm volatile("{\n\t.reg .pred p;\n\t"
        "mbarrier.try_wait.parity.acquire.cluster.shared::cta.b64 p, [%1], %2;\n\t"
        "selp.b32 %0, 1, 0, p;\n\t}"
        : "=r"(done) : "r"(addr), "r"(parity) : "memory");
    if (!done) {
        asm volatile("{\n\t.reg .pred P1;\n\t"
            "W_%=:\n\t"
            "mbarrier.try_wait.parity.acquire.cluster.shared::cta.b64 P1, [%0], %1, 0x989680;\n\t"
            "@P1 bra.uni D_%=;\n\t"
            "bra.uni W_%=;\n\t"
            "D_%=:\n\t}"
            :: "r"(addr), "r"(parity) : "memory");
    }
}
#define CLUSTER_SYNC() do { \
    asm volatile("barrier.cluster.arrive.aligned;" ::: "memory"); \
    asm volatile("barrier.cluster.wait.aligned;"   ::: "memory"); \
} while (0)

__device__ __forceinline__ float wred(float v) {     // full-warp sum
    v += __shfl_xor_sync(0xFFFFFFFFu, v, 16);
    v += __shfl_xor_sync(0xFFFFFFFFu, v, 8);
    v += __shfl_xor_sync(0xFFFFFFFFu, v, 4);
    v += __shfl_xor_sync(0xFFFFFFFFu, v, 2);
    v += __shfl_xor_sync(0xFFFFFFFFu, v, 1);
    return v;
}
__device__ __forceinline__ float gred16(float v) {   // 16-lane group sum (all lanes get it)
    v += __shfl_xor_sync(0xFFFFFFFFu, v, 8);
    v += __shfl_xor_sync(0xFFFFFFFFu, v, 4);
    v += __shfl_xor_sync(0xFFFFFFFFu, v, 2);
    v += __shfl_xor_sync(0xFFFFFFFFu, v, 1);
    return v;
}

// ---- packed f32x2 helpers (FFMA2, PTX-only) ----
__device__ __forceinline__ ull mul2(ull a, ull b) {
    ull d; asm("mul.rn.f32x2 %0, %1, %2;" : "=l"(d) : "l"(a), "l"(b)); return d;
}
__device__ __forceinline__ ull fma2(ull a, ull b, ull c) {
    ull d; asm("fma.rn.f32x2 %0, %1, %2, %3;" : "=l"(d) : "l"(a), "l"(b), "l"(c)); return d;
}
__device__ __forceinline__ float hadd2(ull a) {
    uint32_t lo, hi;
    asm("mov.b64 {%0, %1}, %2;" : "=r"(lo), "=r"(hi) : "l"(a));
    return __uint_as_float(lo) + __uint_as_float(hi);
}
__device__ __forceinline__ void ld2x2(const float* p, int c1, int c2, ull* o) {
    ulonglong2 t0 = *reinterpret_cast<const ulonglong2*>(p + c1);
    ulonglong2 t1 = *reinterpret_cast<const ulonglong2*>(p + c2);
    o[0] = t0.x; o[1] = t0.y; o[2] = t1.x; o[3] = t1.y;
}
__device__ __forceinline__ float dot4p(const ull* k, const ull* x) {
    ull acc = mul2(k[0], x[0]);
    acc = fma2(k[1], x[1], acc);
    acc = fma2(k[2], x[2], acc);
    acc = fma2(k[3], x[3], acc);
    return hadd2(acc);
}
__device__ __forceinline__ float dot8f(float4 a0, float4 a1, float4 b0, float4 b1) {
    float s0 = a0.x * b0.x, s1 = a0.y * b0.y;
    s0 = fmaf(a0.z, b0.z, s0); s1 = fmaf(a0.w, b0.w, s1);
    s0 = fmaf(a1.x, b1.x, s0); s1 = fmaf(a1.y, b1.y, s1);
    s0 = fmaf(a1.z, b1.z, s0); s1 = fmaf(a1.w, b1.w, s1);
    return s0 + s1;
}

__global__ void __launch_bounds__(NTH, 1)
hf_kernel(const float* __restrict__ wfy0, const float* __restrict__ kin,
          const float* __restrict__ vint, const float* __restrict__ uho,
          const float* __restrict__ delx_p, const float* __restrict__ pfac_p,
          const int* __restrict__ iter_p, float* __restrict__ out)
{
    extern __shared__ char smraw[];
    Smem* s = reinterpret_cast<Smem*>(smraw);
    const int tid  = threadIdx.x;
    const int wid  = tid >> 5;
    const int lane = tid & 31;
    uint32_t rank;
    asm("mov.u32 %0, %%cluster_ctarank;" : "=r"(rank));
    const int row0 = (int)rank * RPC;
    const float delx = *delx_p;
    const float pfac = *pfac_p;
    const float rdelx = 1.f / delx;
    const int itermax = *iter_p;

    // ---- init ----
    if (tid == 0) {
        asm volatile("mbarrier.init.shared.b64 [%0], %1;" :: "r"(smem_u32(&s->mbar[0])), "r"(CN) : "memory");
        asm volatile("mbarrier.init.shared.b64 [%0], %1;" :: "r"(smem_u32(&s->mbar[1])), "r"(CN) : "memory");
    }
    for (int i = tid; i < RPAD * NPAD; i += NTH) {
        int r = i >> 8, c = i & 255;
        bool ok = (r < RPC) && (c < NXg);
        s->kin [r][c] = ok ? kin [(row0 + r) * NXg + c] : 0.f;
        s->vint[r][c] = ok ? vint[(row0 + r) * NXg + c] : 0.f;
    }
    for (int c = tid; c < NPAD; c += NTH) {
        float a = (c < NXg) ? wfy0[c * 2 + 0] : 0.f;
        float b = (c < NXg) ? wfy0[c * 2 + 1] : 0.f;
        s->wbuf[0][0][c] = a;   s->wbuf[0][1][c] = b;
        s->wbuf[1][0][c] = 0.f; s->wbuf[1][1][c] = 0.f;
        s->fball[0][0][c] = 0.f; s->fball[0][1][c] = 0.f;
        s->fball[1][0][c] = 0.f; s->fball[1][1][c] = 0.f;
        s->uho[c] = (c < NXg) ? uho[c] : 0.f;
    }
    __syncthreads();
    CLUSTER_SYNC();   // mbar init + zero padding visible cluster-wide

    // 16-lane group per row; lane splits: m = col slice, h = column half
    const int m = lane & 7;
    const int h = (lane >> 3) & 1;
    const int g2 = lane >> 4;          // row within warp (0,1)
    const int row  = (wid << 1) + g2;  // 0..15 (row 15 padded-zero)
    const int gi   = row0 + row;
    const bool active = row < RPC;
    const int tr = lane & 15;          // scatter target rank for this lane
    const int c1 = lane * 4;           // for warp-wide dots (scalar phase / epilogue)
    const int c2 = 128 + lane * 4;

    // hoisted remote addresses (per parity): fb scatter targets rank tr
    uint32_t ra0[2], ra1[2];
    #pragma unroll
    for (int p = 0; p < 2; ++p) {
        ra0[p] = mapa_u32(smem_u32(&s->fball[p][0][gi]), tr);
        ra1[p] = mapa_u32(smem_u32(&s->fball[p][1][gi]), tr);
    }

    for (int it = 0; it < itermax; ++it) {
        const int cur = it & 1, nx = cur ^ 1;
        const float* w0 = s->wbuf[cur][0];
        const float* w1 = s->wbuf[cur][1];

        // ---- RHS slices in registers: lane owns cols h*128 + m*4 + j*32, j=0..3 ----
        ull A[8], B[8];
        #pragma unroll
        for (int j = 0; j < 4; ++j) {
            int c = h * 128 + m * 4 + j * 32;
            ulonglong2 ta = *(const ulonglong2*)(w0 + c);
            ulonglong2 tb = *(const ulonglong2*)(w1 + c);
            A[2*j] = ta.x; A[2*j+1] = ta.y;
            B[2*j] = tb.x; B[2*j+1] = tb.y;
        }

        // ---- matvec: row per 16-lane group ----
        ull kw0 = 0, kw1 = 0, v00 = 0, v01 = 0, v11 = 0;
        const float* kr = s->kin[row];
        const float* vr = s->vint[row];
        #pragma unroll
        for (int j = 0; j < 4; ++j) {
            int c = h * 128 + m * 4 + j * 32;
            ulonglong2 K = *(const ulonglong2*)(kr + c);
            ulonglong2 V = *(const ulonglong2*)(vr + c);
            ull a0 = A[2*j], a1 = A[2*j+1];
            ull b0 = B[2*j], b1 = B[2*j+1];
            kw0 = fma2(K.x, a0, kw0); kw0 = fma2(K.y, a1, kw0);
            kw1 = fma2(K.x, b0, kw1); kw1 = fma2(K.y, b1, kw1);
            v00 = fma2(V.x, mul2(a0, a0), v00); v00 = fma2(V.y, mul2(a1, a1), v00);
            v01 = fma2(V.x, mul2(a0, b0), v01); v01 = fma2(V.y, mul2(a1, b1), v01);
            v11 = fma2(V.x, mul2(b0, b0), v11); v11 = fma2(V.y, mul2(b1, b1), v11);
        }
        float skw0 = gred16(hadd2(kw0));
        float skw1 = gred16(hadd2(kw1));
        float sv00 = gred16(hadd2(v00));
        float sv01 = gred16(hadd2(v01));
        float sv11 = gred16(hadd2(v11));

        // all 16 lanes of the group redundantly finish the row; lane tr -> rank tr
        {
            float w0i = w0[gi], w1i = w1[gi], uh = s->uho[gi];
            float ud  = delx * (sv00 + sv11);
            float hw0 = skw0 - delx * (w0i * sv00 + w1i * sv01) + (ud + uh) * w0i;
            float hw1 = skw1 - delx * (w0i * sv01 + w1i * sv11) + (ud + uh) * w1i;
            float fb0 = w0i - pfac * hw0;
            float fb1 = w1i - pfac * hw1;
            if (active) {
                if (tr == 0) s->udirs[row] = ud;
                st_remote_f32(ra0[cur], fb0);
                st_remote_f32(ra1[cur], fb1);
            }
        }
        __syncthreads();                                  // barA: all scatters issued
        if (tid < CN) mbar_arrive_remote(smem_u32(&s->mbar[cur]), tid);
        mbar_wait_parity(smem_u32(&s->mbar[cur]), (uint32_t)((it >> 1) & 1));

        // ---- 9 global scalars, one warp each, from full fb + local w ----
        {
            const float* f0a = s->fball[cur][0];
            const float* f1a = s->fball[cur][1];
            const float* xs; const float* ys;
            switch (wid) {
                case 0:  xs = f0a; ys = f0a; break;   // S0
                case 1:  xs = f1a; ys = f1a; break;   // S1
                case 2:  xs = f0a; ys = f1a; break;   // Xs
                case 3:  xs = w0;  ys = f1a; break;   // Ys
                case 4:  xs = f0a; ys = w0;  break;   // Zs
                case 5:  xs = w0;  ys = w0;  break;   // W2
                case 6:  xs = w1;  ys = w1;  break;   // V2
                default: xs = w1;  ys = f1a; break;   // Us
            }
            float4 X0 = *(const float4*)(xs + c1), X1 = *(const float4*)(xs + c2);
            float4 Y0 = *(const float4*)(ys + c1), Y1 = *(const float4*)(ys + c2);
            float v = dot8f(X0, X1, Y0, Y1);
            v = wred(v);
            if (lane == 0) s->scal[wid] = v;
            if (wid == 0) {   // EH = sum (w0^2 + w1^2) * uho
                float4 P0 = *(const float4*)(w0 + c1), P1 = *(const float4*)(w0 + c2);
                float4 Q0 = *(const float4*)(w1 + c1), Q1 = *(const float4*)(w1 + c2);
                float4 U0 = *(const float4*)(s->uho + c1), U1 = *(const float4*)(s->uho + c2);
                float e = (P0.x*P0.x + Q0.x*Q0.x) * U0.x;
                e = fmaf(P0.y*P0.y + Q0.y*Q0.y, U0.y, e);
                e = fmaf(P0.z*P0.z + Q0.z*Q0.z, U0.z, e);
                e = fmaf(P0.w*P0.w + Q0.w*Q0.w, U0.w, e);
                e = fmaf(P1.x*P1.x + Q1.x*Q1.x, U1.x, e);
                e = fmaf(P1.y*P1.y + Q1.y*Q1.y, U1.y, e);
                e = fmaf(P1.z*P1.z + Q1.z*Q1.z, U1.z, e);
                e = fmaf(P1.w*P1.w + Q1.w*Q1.w, U1.w, e);
                e = wred(e);
                if (lane == 0) s->scal[8] = e;
            }
        }
        __syncthreads();                                  // barB: scalars ready

        // ---- update: every element thread, closed-form chain redundant ----
        if (tid < NXg) {
            float S0 = s->scal[0], S1 = s->scal[1], Xs = s->scal[2];
            float Ys = s->scal[3], Zs = s->scal[4], W2 = s->scal[5];
            float inv0 = rsqrtf(S0 * delx);
            float inv1 = rsqrtf(S1 * delx);
            float dGS  = FFACf * inv0 * inv1 * Xs + OMFf * inv1 * Ys;
            float sn0  = 0.16f * rdelx + 0.48f * inv0 * Zs + 0.36f * W2;
            float T1   = rdelx - dGS * dGS * delx * (2.f - delx * sn0);
            float invT1d = __fdividef(1.f, T1 * delx);
            float a0 = FFACf * inv0;
            float b1 = FFACf * invT1d * inv1;
            float cc = FFACf * invT1d * dGS * delx;
            float fb0 = s->fball[cur][0][tid];
            float fb1 = s->fball[cur][1][tid];
            float n0 = a0 * fb0 + OMFf * w0[tid];
            float n1 = b1 * fb1 - cc * n0 + OMFf * w1[tid];
            s->wbuf[nx][0][tid] = n0;
            s->wbuf[nx][1][tid] = n1;
        }
        __syncthreads();                                  // barC: wbuf[nx] ready
    }

    // ---- final energies: ekin = new.K.new, epot = new.Umf.new ----
    {
        const int fin = itermax & 1, oldp = fin ^ 1;
        const float* wo0 = s->wbuf[oldp][0]; const float* wo1 = s->wbuf[oldp][1];
        const float* nv0 = s->wbuf[fin][0];  const float* nv1 = s->wbuf[fin][1];
        ull Ao[4], Bo[4], N0[4], N1[4], P0[4], P1[4], Q0[4], Q1[4];
        ld2x2(wo0, c1, c2, Ao);
        ld2x2(wo1, c1, c2, Bo);
        ld2x2(nv0, c1, c2, N0);
        ld2x2(nv1, c1, c2, N1);
        #pragma unroll
        for (int i = 0; i < 4; ++i) {
            P0[i] = mul2(Ao[i], N0[i]);
            P1[i] = mul2(Bo[i], N0[i]);
            Q0[i] = mul2(Ao[i], N1[i]);
            Q1[i] = mul2(Bo[i], N1[i]);
        }
        float pek = 0.f, pep = 0.f;
        for (int r = wid; r < RPC; r += NW) {
            ull K[4], V[4];
            ld2x2(s->kin[r],  c1, c2, K);
            ld2x2(s->vint[r], c1, c2, V);
            float kn0 = dot4p(K, N0), kn1 = dot4p(K, N1);
            float q00 = dot4p(V, P0), q10 = dot4p(V, P1);
            float q01 = dot4p(V, Q0), q11 = dot4p(V, Q1);
            kn0 = wred(kn0); kn1 = wred(kn1);
            q00 = wred(q00); q10 = wred(q10);
            q01 = wred(q01); q11 = wred(q11);
            if (lane == 0) {
                int gr = row0 + r;
                float n0i = nv0[gr], n1i = nv1[gr];
                float w0o = wo0[gr], w1o = wo1[gr];
                float diag = s->udirs[r] + s->uho[gr];
                float um0 = -delx * (w0o * q00 + w1o * q10) + diag * n0i;
                float um1 = -delx * (w0o * q01 + w1o * q11) + diag * n1i;
                pek += n0i * kn0 + n1i * kn1;
                pep += n0i * um0 + n1i * um1;
            }
        }
        if (lane == 0) { s->wred2[wid][0] = pek; s->wred2[wid][1] = pep; }
        __syncthreads();
        if (tid < 2) {
            float v = 0.f;
            #pragma unroll
            for (int w = 0; w < NW; ++w) v += s->wred2[w][tid];
            uint32_t la = smem_u32(&s->redF[rank][tid]);
            #pragma unroll
            for (int t = 0; t < CN; ++t) st_cluster_f32(la, t, v);
        }
        CLUSTER_SYNC();
        if (rank == 0 && tid == 0) {
            float EK = 0.f, EP = 0.f;
            for (int rr = 0; rr < CN; ++rr) { EK += s->redF[rr][0]; EP += s->redF[rr][1]; }
            // last-iteration scalars are replicated in every CTA's s->scal
            float Zs = s->scal[4], W2 = s->scal[5], V2 = s->scal[6];
            float Us = s->scal[7], EH = s->scal[8];
            float esum = ((W2 - Zs) + (V2 - Us)) / pfac * delx;
            float eho  = EH * delx * 0.5f;
            float ekin = EK * delx;
            float epot = EP * delx;
            float enerhfp = (esum + ekin) * 0.5f + eho;
            float epot0   = epot - 2.f * eho;
            float enerhf  = esum - epot0 * 0.5f;
            out[0] = enerhf; out[1] = enerhfp; out[2] = ekin;
            out[3] = eho;    out[4] = epot0;   out[5] = esum;
        }
    }
}

extern "C" void kernel_launch(void* const* d_in, const int* in_sizes, int n_in,
                              void* d_out, int out_size) {
    (void)in_sizes; (void)n_in; (void)out_size;
    cudaFuncSetAttribute(hf_kernel, cudaFuncAttributeMaxDynamicSharedMemorySize,
                         (int)sizeof(Smem));
    cudaFuncSetAttribute(hf_kernel, cudaFuncAttributeNonPortableClusterSizeAllowed, 1);

    cudaLaunchConfig_t cfg = {};
    cfg.gridDim = dim3(CN, 1, 1);
    cfg.blockDim = dim3(NTH, 1, 1);
    cfg.dynamicSmemBytes = sizeof(Smem);
    cudaLaunchAttribute attrs[1];
    attrs[0].id = cudaLaunchAttributeClusterDimension;
    attrs[0].val.clusterDim = {CN, 1, 1};
    cfg.attrs = attrs;
    cfg.numAttrs = 1;

    cudaLaunchKernelEx(&cfg, hf_kernel,
        (const float*)d_in[0],   // wfy0 (240,2)
        (const float*)d_in[1],   // kin_mat (240,240)
        (const float*)d_in[2],   // Vint (240,240)
        (const float*)d_in[3],   // U_HO (240)
        (const float*)d_in[4],   // delx
        (const float*)d_in[5],   // pfac
        (const int*)d_in[6],     // itermax
        (float*)d_out);          // 6 outputs
}

// round 11
// speedup vs baseline: 1.1880x; 1.1880x over previous
#include <cuda_runtime.h>
#include <cstdint>

#define NXg   240
#define NPAD  256
#define CN    8      // cluster size (CTAs)
#define RPC   30     // rows per CTA
#define RPAD  32     // padded row count (rows 30,31 zero)
#define NTH   256    // 8 warps
#define NW    8
#define FFACf 0.4f
#define OMFf  0.6f

typedef unsigned long long ull;

struct __align__(16) Smem {
    alignas(16) ull   mbar[2];            // ping-pong cluster barriers (count=8)
    alignas(16) float scal[12];           // 9 global scalars (per-CTA replicated)
    alignas(16) float udirs[32];
    alignas(16) float wred2[NW][2];
    alignas(16) float redF[CN][2];        // final-energy cluster slots
    alignas(16) float uho [NPAD];
    alignas(16) float wbuf [2][2][NPAD];  // ping-pong wavefunctions (local)
    alignas(16) float fball[2][2][NPAD];  // ping-pong broadcast fb vectors (DSMEM-filled)
    alignas(16) float kin [RPAD][NPAD];
    alignas(16) float vint[RPAD][NPAD];
};

__device__ __forceinline__ uint32_t smem_u32(const void* p) {
    return (uint32_t)__cvta_generic_to_shared(p);
}
__device__ __forceinline__ uint32_t mapa_u32(uint32_t laddr, int rank) {
    uint32_t r;
    asm("mapa.shared::cluster.u32 %0, %1, %2;" : "=r"(r) : "r"(laddr), "r"(rank));
    return r;
}
__device__ __forceinline__ void st_remote_f32(uint32_t raddr, float v) {
    asm volatile("st.shared::cluster.u32 [%0], %1;" :: "r"(raddr), "r"(__float_as_uint(v)) : "memory");
}
__device__ __forceinline__ void st_cluster_f32(uint32_t laddr, int rank, float v) {
    st_remote_f32(mapa_u32(laddr, rank), v);
}
__device__ __forceinline__ void mbar_arrive_remote(uint32_t laddr, int rank) {
    asm volatile("{\n\t.reg .b32 ra;\n\t"
        "mapa.shared::cluster.u32 ra, %0, %1;\n\t"
        "mbarrier.arrive.release.cluster.shared::cluster.b64 _, [ra];\n\t}"
        :: "r"(laddr), "r"(rank) : "memory");
}
__device__ __forceinline__ void mbar_wait_parity(uint32_t addr, uint32_t parity) {
    uint32_t done;
    asm volatile("{\n\t.reg .pred p;\n\t"
        "mbarrier.try_wait.parity.acquire.cluster.shared::cta.b64 p, [%1], %2;\n\t"
        "selp.b32 %0, 1, 0, p;\n\t}"
        : "=r"(done) : "r"(addr), "r"(parity) : "memory");
    if (!done) {
        asm volatile("{\n\t.reg .pred P1;\n\t"
            "W_%=:\n\t"
            "mbarrier.try_wait.parity.acquire.cluster.shared::cta.b64 P1, [%0], %1, 0x989680;\n\t"
            "@P1 bra.uni D_%=;\n\t"
            "bra.uni W_%=;\n\t"
            "D_%=:\n\t}"
            :: "r"(addr), "r"(parity) : "memory");
    }
}
#define CLUSTER_SYNC() do { \
    asm volatile("barrier.cluster.arrive.aligned;" ::: "memory"); \
    asm volatile("barrier.cluster.wait.aligned;"   ::: "memory"); \
} while (0)

__device__ __forceinline__ float wred(float v) {     // full-warp sum
    v += __shfl_xor_sync(0xFFFFFFFFu, v, 16);
    v += __shfl_xor_sync(0xFFFFFFFFu, v, 8);
    v += __shfl_xor_sync(0xFFFFFFFFu, v, 4);
    v += __shfl_xor_sync(0xFFFFFFFFu, v, 2);
    v += __shfl_xor_sync(0xFFFFFFFFu, v, 1);
    return v;
}
__device__ __forceinline__ float gred(float v) {     // 8-lane group sum (all lanes get it)
    v += __shfl_xor_sync(0xFFFFFFFFu, v, 4);
    v += __shfl_xor_sync(0xFFFFFFFFu, v, 2);
    v += __shfl_xor_sync(0xFFFFFFFFu, v, 1);
    return v;
}

// ---- packed f32x2 helpers (FFMA2, PTX-only) ----
__device__ __forceinline__ ull mul2(ull a, ull b) {
    ull d; asm("mul.rn.f32x2 %0, %1, %2;" : "=l"(d) : "l"(a), "l"(b)); return d;
}
__device__ __forceinline__ ull fma2(ull a, ull b, ull c) {
    ull d; asm("fma.rn.f32x2 %0, %1, %2, %3;" : "=l"(d) : "l"(a), "l"(b), "l"(c)); return d;
}
__device__ __forceinline__ float hadd2(ull a) {
    uint32_t lo, hi;
    asm("mov.b64 {%0, %1}, %2;" : "=r"(lo), "=r"(hi) : "l"(a));
    return __uint_as_float(lo) + __uint_as_float(hi);
}
__device__ __forceinline__ void ld2x2(const float* p, int c1, int c2, ull* o) {
    ulonglong2 t0 = *reinterpret_cast<const ulonglong2*>(p + c1);
    ulonglong2 t1 = *reinterpret_cast<const ulonglong2*>(p + c2);
    o[0] = t0.x; o[1] = t0.y; o[2] = t1.x; o[3] = t1.y;
}
__device__ __forceinline__ float dot4p(const ull* k, const ull* x) {
    ull acc = mul2(k[0], x[0]);
    acc = fma2(k[1], x[1], acc);
    acc = fma2(k[2], x[2], acc);
    acc = fma2(k[3], x[3], acc);
    return hadd2(acc);
}
__device__ __forceinline__ float dot8f(float4 a0, float4 a1, float4 b0, float4 b1) {
    float s0 = a0.x * b0.x, s1 = a0.y * b0.y;
    s0 = fmaf(a0.z, b0.z, s0); s1 = fmaf(a0.w, b0.w, s1);
    s0 = fmaf(a1.x, b1.x, s0); s1 = fmaf(a1.y, b1.y, s1);
    s0 = fmaf(a1.z, b1.z, s0); s1 = fmaf(a1.w, b1.w, s1);
    return s0 + s1;
}

__global__ void __launch_bounds__(NTH, 1) __cluster_dims__(CN, 1, 1)
hf_kernel(const float* __restrict__ wfy0, const float* __restrict__ kin,
          const float* __restrict__ vint, const float* __restrict__ uho,
          const float* __restrict__ delx_p, const float* __restrict__ pfac_p,
          const int* __restrict__ iter_p, float* __restrict__ out)
{
    extern __shared__ char smraw[];
    Smem* s = reinterpret_cast<Smem*>(smraw);
    const int tid  = threadIdx.x;
    const int wid  = tid >> 5;
    const int lane = tid & 31;
    uint32_t rank;
    asm("mov.u32 %0, %%cluster_ctarank;" : "=r"(rank));
    const int row0 = (int)rank * RPC;
    const float delx = *delx_p;
    const float pfac = *pfac_p;
    const float rdelx = 1.f / delx;
    const int itermax = *iter_p;

    // ---- init ----
    if (tid == 0) {
        asm volatile("mbarrier.init.shared.b64 [%0], %1;" :: "r"(smem_u32(&s->mbar[0])), "r"(CN) : "memory");
        asm volatile("mbarrier.init.shared.b64 [%0], %1;" :: "r"(smem_u32(&s->mbar[1])), "r"(CN) : "memory");
    }
    for (int i = tid; i < RPAD * NPAD; i += NTH) {
        int r = i >> 8, c = i & 255;
        bool ok = (r < RPC) && (c < NXg);
        s->kin [r][c] = ok ? kin [(row0 + r) * NXg + c] : 0.f;
        s->vint[r][c] = ok ? vint[(row0 + r) * NXg + c] : 0.f;
    }
    for (int c = tid; c < NPAD; c += NTH) {
        float a = (c < NXg) ? wfy0[c * 2 + 0] : 0.f;
        float b = (c < NXg) ? wfy0[c * 2 + 1] : 0.f;
        s->wbuf[0][0][c] = a;   s->wbuf[0][1][c] = b;
        s->wbuf[1][0][c] = 0.f; s->wbuf[1][1][c] = 0.f;
        s->fball[0][0][c] = 0.f; s->fball[0][1][c] = 0.f;
        s->fball[1][0][c] = 0.f; s->fball[1][1][c] = 0.f;
        s->uho[c] = (c < NXg) ? uho[c] : 0.f;
    }
    __syncthreads();
    CLUSTER_SYNC();   // mbar init + zero padding visible cluster-wide

    const int m = lane & 7;            // column-slice owner within 8-lane group
    const int g = lane >> 3;           // row group within warp
    const int row  = (wid << 2) + g;   // 0..31 (30,31 padded-zero rows)
    const int gi   = row0 + row;
    const bool active = row < RPC;
    const int c1 = lane * 4;           // for warp-wide dots (scalar phase / epilogue)
    const int c2 = 128 + lane * 4;

    // hoisted remote scatter addresses (per parity, target rank = m)
    uint32_t ra0[2], ra1[2];
    #pragma unroll
    for (int p = 0; p < 2; ++p) {
        ra0[p] = mapa_u32(smem_u32(&s->fball[p][0][gi]), m);
        ra1[p] = mapa_u32(smem_u32(&s->fball[p][1][gi]), m);
    }

    for (int it = 0; it < itermax; ++it) {
        const int cur = it & 1, nx = cur ^ 1;
        const float* w0 = s->wbuf[cur][0];
        const float* w1 = s->wbuf[cur][1];

        // ---- RHS vectors in registers (same columns for all groups) ----
        ull A[16], B[16];
        #pragma unroll
        for (int j = 0; j < 8; ++j) {
            int c = m * 4 + j * 32;
            ulonglong2 ta = *(const ulonglong2*)(w0 + c);
            ulonglong2 tb = *(const ulonglong2*)(w1 + c);
            A[2*j] = ta.x; A[2*j+1] = ta.y;
            B[2*j] = tb.x; B[2*j+1] = tb.y;
        }

        // ---- matvec: row per 8-lane group; only K,V touched in SMEM ----
        ull kw0 = 0, kw1 = 0, v00 = 0, v01 = 0, v11 = 0;
        const float* kr = s->kin[row];
        const float* vr = s->vint[row];
        #pragma unroll
        for (int j = 0; j < 8; ++j) {
            int c = m * 4 + j * 32;
            ulonglong2 K = *(const ulonglong2*)(kr + c);
            ulonglong2 V = *(const ulonglong2*)(vr + c);
            ull a0 = A[2*j], a1 = A[2*j+1];
            ull b0 = B[2*j], b1 = B[2*j+1];
            kw0 = fma2(K.x, a0, kw0); kw0 = fma2(K.y, a1, kw0);
            kw1 = fma2(K.x, b0, kw1); kw1 = fma2(K.y, b1, kw1);
            v00 = fma2(V.x, mul2(a0, a0), v00); v00 = fma2(V.y, mul2(a1, a1), v00);
            v01 = fma2(V.x, mul2(a0, b0), v01); v01 = fma2(V.y, mul2(a1, b1), v01);
            v11 = fma2(V.x, mul2(b0, b0), v11); v11 = fma2(V.y, mul2(b1, b1), v11);
        }
        float skw0 = gred(hadd2(kw0));
        float skw1 = gred(hadd2(kw1));
        float sv00 = gred(hadd2(v00));
        float sv01 = gred(hadd2(v01));
        float sv11 = gred(hadd2(v11));

        // all 8 lanes of the group redundantly finish the row; lane m -> rank m
        {
            float w0i = w0[gi], w1i = w1[gi], uh = s->uho[gi];
            float ud  = delx * (sv00 + sv11);
            float hw0 = skw0 - delx * (w0i * sv00 + w1i * sv01) + (ud + uh) * w0i;
            float hw1 = skw1 - delx * (w0i * sv01 + w1i * sv11) + (ud + uh) * w1i;
            float fb0 = w0i - pfac * hw0;
            float fb1 = w1i - pfac * hw1;
            if (active) {
                if (m == 0) s->udirs[row] = ud;
                st_remote_f32(ra0[cur], fb0);
                st_remote_f32(ra1[cur], fb1);
            }
        }
        __syncthreads();                                  // barA: all scatters issued
        if (tid < CN) mbar_arrive_remote(smem_u32(&s->mbar[cur]), tid);

        // ---- pre-wait: local-only scalars (W2,V2,EH) + preload local halves ----
        float4 L0, L1;   // preloaded local operand for wid 3 (w0), 4 (w0), 5 (w1)
        if (wid == 3 || wid == 4) { L0 = *(const float4*)(w0 + c1); L1 = *(const float4*)(w0 + c2); }
        else if (wid == 5)        { L0 = *(const float4*)(w1 + c1); L1 = *(const float4*)(w1 + c2); }
        if (wid == 6) {          // W2 = w0.w0
            float4 X0 = *(const float4*)(w0 + c1), X1 = *(const float4*)(w0 + c2);
            float v = wred(dot8f(X0, X1, X0, X1));
            if (lane == 0) s->scal[5] = v;
        } else if (wid == 7) {   // V2 = w1.w1  and EH = sum (w0^2+w1^2)*uho
            float4 X0 = *(const float4*)(w1 + c1), X1 = *(const float4*)(w1 + c2);
            float v = wred(dot8f(X0, X1, X0, X1));
            float4 P0 = *(const float4*)(w0 + c1), P1 = *(const float4*)(w0 + c2);
            float4 U0 = *(const float4*)(s->uho + c1), U1 = *(const float4*)(s->uho + c2);
            float e = (P0.x*P0.x + X0.x*X0.x) * U0.x;
            e = fmaf(P0.y*P0.y + X0.y*X0.y, U0.y, e);
            e = fmaf(P0.z*P0.z + X0.z*X0.z, U0.z, e);
            e = fmaf(P0.w*P0.w + X0.w*X0.w, U0.w, e);
            e = fmaf(P1.x*P1.x + X1.x*X1.x, U1.x, e);
            e = fmaf(P1.y*P1.y + X1.y*X1.y, U1.y, e);
            e = fmaf(P1.z*P1.z + X1.z*X1.z, U1.z, e);
            e = fmaf(P1.w*P1.w + X1.w*X1.w, U1.w, e);
            e = wred(e);
            if (lane == 0) { s->scal[6] = v; s->scal[8] = e; }
        }

        mbar_wait_parity(smem_u32(&s->mbar[cur]), (uint32_t)((it >> 1) & 1));

        // ---- post-wait: 6 remote-dependent scalars, one warp each ----
        if (wid < 6) {
            const float* f0a = s->fball[cur][0];
            const float* f1a = s->fball[cur][1];
            float v;
            if (wid == 0) {        // S0 = fb0.fb0
                float4 X0 = *(const float4*)(f0a + c1), X1 = *(const float4*)(f0a + c2);
                v = dot8f(X0, X1, X0, X1);
            } else if (wid == 1) { // S1 = fb1.fb1
                float4 X0 = *(const float4*)(f1a + c1), X1 = *(const float4*)(f1a + c2);
                v = dot8f(X0, X1, X0, X1);
            } else if (wid == 2) { // Xs = fb0.fb1
                float4 X0 = *(const float4*)(f0a + c1), X1 = *(const float4*)(f0a + c2);
                float4 Y0 = *(const float4*)(f1a + c1), Y1 = *(const float4*)(f1a + c2);
                v = dot8f(X0, X1, Y0, Y1);
            } else if (wid == 3) { // Ys = w0.fb1  (L = w0 preloaded)
                float4 Y0 = *(const float4*)(f1a + c1), Y1 = *(const float4*)(f1a + c2);
                v = dot8f(L0, L1, Y0, Y1);
            } else if (wid == 4) { // Zs = fb0.w0  (L = w0 preloaded)
                float4 Y0 = *(const float4*)(f0a + c1), Y1 = *(const float4*)(f0a + c2);
                v = dot8f(L0, L1, Y0, Y1);
            } else {               // Us = w1.fb1  (L = w1 preloaded)
                float4 Y0 = *(const float4*)(f1a + c1), Y1 = *(const float4*)(f1a + c2);
                v = dot8f(L0, L1, Y0, Y1);
            }
            v = wred(v);
            if (lane == 0) {
                int idx = (wid < 5) ? wid : 7;   // S0,S1,Xs,Ys,Zs -> 0..4 ; Us -> 7
                s->scal[idx] = v;
            }
        }
        __syncthreads();                                  // barB: scalars ready

        // ---- update: every element thread, closed-form chain redundant ----
        if (tid < NXg) {
            float S0 = s->scal[0], S1 = s->scal[1], Xs = s->scal[2];
            float Ys = s->scal[3], Zs = s->scal[4], W2 = s->scal[5];
            float inv0 = rsqrtf(S0 * delx);
            float inv1 = rsqrtf(S1 * delx);
            float dGS  = FFACf * inv0 * inv1 * Xs + OMFf * inv1 * Ys;
            float sn0  = 0.16f * rdelx + 0.48f * inv0 * Zs + 0.36f * W2;
            float T1   = rdelx - dGS * dGS * delx * (2.f - delx * sn0);
            float invT1d = __fdividef(1.f, T1 * delx);
            float a0 = FFACf * inv0;
            float b1 = FFACf * invT1d * inv1;
            float cc = FFACf * invT1d * dGS * delx;
            float fb0 = s->fball[cur][0][tid];
            float fb1 = s->fball[cur][1][tid];
            float n0 = a0 * fb0 + OMFf * w0[tid];
            float n1 = b1 * fb1 - cc * n0 + OMFf * w1[tid];
            s->wbuf[nx][0][tid] = n0;
            s->wbuf[nx][1][tid] = n1;
        }
        __syncthreads();                                  // barC: wbuf[nx] ready
    }

    // ---- final energies: ekin = new.K.new, epot = new.Umf.new ----
    {
        const int fin = itermax & 1, oldp = fin ^ 1;
        const float* wo0 = s->wbuf[oldp][0]; const float* wo1 = s->wbuf[oldp][1];
        const float* nv0 = s->wbuf[fin][0];  const float* nv1 = s->wbuf[fin][1];
        ull Ao[4], Bo[4], N0[4], N1[4], P0[4], P1[4], Q0[4], Q1[4];
        ld2x2(wo0, c1, c2, Ao);
        ld2x2(wo1, c1, c2, Bo);
        ld2x2(nv0, c1, c2, N0);
        ld2x2(nv1, c1, c2, N1);
        #pragma unroll
        for (int i = 0; i < 4; ++i) {
            P0[i] = mul2(Ao[i], N0[i]);
            P1[i] = mul2(Bo[i], N0[i]);
            Q0[i] = mul2(Ao[i], N1[i]);
            Q1[i] = mul2(Bo[i], N1[i]);
        }
        float pek = 0.f, pep = 0.f;
        for (int r = wid; r < RPC; r += NW) {
            ull K[4], V[4];
            ld2x2(s->kin[r],  c1, c2, K);
            ld2x2(s->vint[r], c1, c2, V);
            float kn0 = dot4p(K, N0), kn1 = dot4p(K, N1);
            float q00 = dot4p(V, P0), q10 = dot4p(V, P1);
            float q01 = dot4p(V, Q0), q11 = dot4p(V, Q1);
            kn0 = wred(kn0); kn1 = wred(kn1);
            q00 = wred(q00); q10 = wred(q10);
            q01 = wred(q01); q11 = wred(q11);
            if (lane == 0) {
                int gr = row0 + r;
                float n0i = nv0[gr], n1i = nv1[gr];
                float w0o = wo0[gr], w1o = wo1[gr];
                float diag = s->udirs[r] + s->uho[gr];
                float um0 = -delx * (w0o * q00 + w1o * q10) + diag * n0i;
                float um1 = -delx * (w0o * q01 + w1o * q11) + diag * n1i;
                pek += n0i * kn0 + n1i * kn1;
                pep += n0i * um0 + n1i * um1;
            }
        }
        if (lane == 0) { s->wred2[wid][0] = pek; s->wred2[wid][1] = pep; }
        __syncthreads();
        if (tid < 2) {
            float v = 0.f;
            #pragma unroll
            for (int w = 0; w < NW; ++w) v += s->wred2[w][tid];
            uint32_t la = smem_u32(&s->redF[rank][tid]);
            #pragma unroll
            for (int tr = 0; tr < CN; ++tr) st_cluster_f32(la, tr, v);
        }
        CLUSTER_SYNC();
        if (rank == 0 && tid == 0) {
            float EK = 0.f, EP = 0.f;
            for (int rr = 0; rr < CN; ++rr) { EK += s->redF[rr][0]; EP += s->redF[rr][1]; }
            // last-iteration scalars are replicated in every CTA's s->scal
            float Zs = s->scal[4], W2 = s->scal[5], V2 = s->scal[6];
            float Us = s->scal[7], EH = s->scal[8];
            float esum = ((W2 - Zs) + (V2 - Us)) / pfac * delx;
            float eho  = EH * delx * 0.5f;
            float ekin = EK * delx;
            float epot = EP * delx;
            float enerhfp = (esum + ekin) * 0.5f + eho;
            float epot0   = epot - 2.f * eho;
            float enerhf  = esum - epot0 * 0.5f;
            out[0] = enerhf; out[1] = enerhfp; out[2] = ekin;
            out[3] = eho;    out[4] = epot0;   out[5] = esum;
        }
    }
}

extern "C" void kernel_launch(void* const* d_in, const int* in_sizes, int n_in,
                              void* d_out, int out_size) {
    (void)in_sizes; (void)n_in; (void)out_size;
    cudaFuncSetAttribute(hf_kernel, cudaFuncAttributeMaxDynamicSharedMemorySize,
                         (int)sizeof(Smem));
    hf_kernel<<<CN, NTH, sizeof(Smem)>>>(
        (const float*)d_in[0],   // wfy0 (240,2)
        (const float*)d_in[1],   // kin_mat (240,240)
        (const float*)d_in[2],   // Vint (240,240)
        (const float*)d_in[3],   // U_HO (240)
        (const float*)d_in[4],   // delx
        (const float*)d_in[5],   // pfac
        (const int*)d_in[6],     // itermax
        (float*)d_out);          // 6 outputs
}

// round 12
// speedup vs baseline: 1.3279x; 1.1178x over previous
#include <cuda_runtime.h>
#include <cstdint>

#define NXg   240
#define NPAD  256
#define CN    8      // cluster size (CTAs)
#define RPC   30     // rows per CTA
#define RPAD  32     // padded row count (rows 30,31 zero)
#define NTH   256    // 8 warps
#define NW    8
#define FFACf 0.4f
#define OMFf  0.6f

typedef unsigned long long ull;

struct __align__(16) Smem {
    alignas(16) ull   mbar[2];            // ping-pong cluster barriers (count=8)
    alignas(16) float scal[12];           // 9 global scalars (per-CTA replicated)
    alignas(16) float udirs[32];
    alignas(16) float wred2[NW][2];
    alignas(16) float redF[CN][2];        // final-energy cluster slots
    alignas(16) float uho [NPAD];
    alignas(16) float wbuf [2][2][NPAD];  // ping-pong wavefunctions (local)
    alignas(16) float fball[2][2][NPAD];  // ping-pong broadcast fb vectors (DSMEM-filled)
    alignas(16) float kin [RPAD][NPAD];
    alignas(16) float vint[RPAD][NPAD];
};

__device__ __forceinline__ uint32_t smem_u32(const void* p) {
    return (uint32_t)__cvta_generic_to_shared(p);
}
__device__ __forceinline__ uint32_t mapa_u32(uint32_t laddr, int rank) {
    uint32_t r;
    asm("mapa.shared::cluster.u32 %0, %1, %2;" : "=r"(r) : "r"(laddr), "r"(rank));
    return r;
}
__device__ __forceinline__ void st_remote_f32(uint32_t raddr, float v) {
    asm volatile("st.shared::cluster.u32 [%0], %1;" :: "r"(raddr), "r"(__float_as_uint(v)) : "memory");
}
__device__ __forceinline__ void st_cluster_f32(uint32_t laddr, int rank, float v) {
    st_remote_f32(mapa_u32(laddr, rank), v);
}
__device__ __forceinline__ void mbar_arrive_remote(uint32_t laddr, int rank) {
    asm volatile("{\n\t.reg .b32 ra;\n\t"
        "mapa.shared::cluster.u32 ra, %0, %1;\n\t"
        "mbarrier.arrive.release.cluster.shared::cluster.b64 _, [ra];\n\t}"
        :: "r"(laddr), "r"(rank) : "memory");
}
__device__ __forceinline__ void mbar_wait_parity(uint32_t addr, uint32_t parity) {
    uint32_t done;
    asm volatile("{\n\t.reg .pred p;\n\t"
        "mbarrier.try_wait.parity.acquire.cluster.shared::cta.b64 p, [%1], %2;\n\t"
        "selp.b32 %0, 1, 0, p;\n\t}"
        : "=r"(done) : "r"(addr), "r"(parity) : "memory");
    if (!done) {
        asm volatile("{\n\t.reg .pred P1;\n\t"
            "W_%=:\n\t"
            "mbarrier.try_wait.parity.acquire.cluster.shared::cta.b64 P1, [%0], %1, 0x989680;\n\t"
            "@P1 bra.uni D_%=;\n\t"
            "bra.uni W_%=;\n\t"
            "D_%=:\n\t}"
            :: "r"(addr), "r"(parity) : "memory");
    }
}
#define CLUSTER_SYNC() do { \
    asm volatile("barrier.cluster.arrive.aligned;" ::: "memory"); \
    asm volatile("barrier.cluster.wait.aligned;"   ::: "memory"); \
} while (0)

__device__ __forceinline__ float wred(float v) {     // full-warp sum
    v += __shfl_xor_sync(0xFFFFFFFFu, v, 16);
    v += __shfl_xor_sync(0xFFFFFFFFu, v, 8);
    v += __shfl_xor_sync(0xFFFFFFFFu, v, 4);
    v += __shfl_xor_sync(0xFFFFFFFFu, v, 2);
    v += __shfl_xor_sync(0xFFFFFFFFu, v, 1);
    return v;
}
__device__ __forceinline__ float gred(float v) {     // 8-lane group sum (all lanes get it)
    v += __shfl_xor_sync(0xFFFFFFFFu, v, 4);
    v += __shfl_xor_sync(0xFFFFFFFFu, v, 2);
    v += __shfl_xor_sync(0xFFFFFFFFu, v, 1);
    return v;
}

// ---- packed f32x2 helpers (FFMA2, PTX-only) ----
__device__ __forceinline__ ull mul2(ull a, ull b) {
    ull d; asm("mul.rn.f32x2 %0, %1, %2;" : "=l"(d) : "l"(a), "l"(b)); return d;
}
__device__ __forceinline__ ull fma2(ull a, ull b, ull c) {
    ull d; asm("fma.rn.f32x2 %0, %1, %2, %3;" : "=l"(d) : "l"(a), "l"(b), "l"(c)); return d;
}
__device__ __forceinline__ float hadd2(ull a) {
    uint32_t lo, hi;
    asm("mov.b64 {%0, %1}, %2;" : "=r"(lo), "=r"(hi) : "l"(a));
    return __uint_as_float(lo) + __uint_as_float(hi);
}
__device__ __forceinline__ void ld2x2(const float* p, int c1, int c2, ull* o) {
    ulonglong2 t0 = *reinterpret_cast<const ulonglong2*>(p + c1);
    ulonglong2 t1 = *reinterpret_cast<const ulonglong2*>(p + c2);
    o[0] = t0.x; o[1] = t0.y; o[2] = t1.x; o[3] = t1.y;
}
__device__ __forceinline__ float dot4p(const ull* k, const ull* x) {
    ull acc = mul2(k[0], x[0]);
    acc = fma2(k[1], x[1], acc);
    acc = fma2(k[2], x[2], acc);
    acc = fma2(k[3], x[3], acc);
    return hadd2(acc);
}
__device__ __forceinline__ float dot8f(float4 a0, float4 a1, float4 b0, float4 b1) {
    float s0 = a0.x * b0.x, s1 = a0.y * b0.y;
    s0 = fmaf(a0.z, b0.z, s0); s1 = fmaf(a0.w, b0.w, s1);
    s0 = fmaf(a1.x, b1.x, s0); s1 = fmaf(a1.y, b1.y, s1);
    s0 = fmaf(a1.z, b1.z, s0); s1 = fmaf(a1.w, b1.w, s1);
    return s0 + s1;
}

__global__ void __launch_bounds__(NTH, 1) __cluster_dims__(CN, 1, 1)
hf_kernel(const float* __restrict__ wfy0, const float* __restrict__ kin,
          const float* __restrict__ vint, const float* __restrict__ uho,
          const float* __restrict__ delx_p, const float* __restrict__ pfac_p,
          const int* __restrict__ iter_p, float* __restrict__ out)
{
    extern __shared__ char smraw[];
    Smem* s = reinterpret_cast<Smem*>(smraw);
    const int tid  = threadIdx.x;
    const int wid  = tid >> 5;
    const int lane = tid & 31;
    uint32_t rank;
    asm("mov.u32 %0, %%cluster_ctarank;" : "=r"(rank));
    const int row0 = (int)rank * RPC;
    const float delx = *delx_p;
    const float pfac = *pfac_p;
    const float rdelx = 1.f / delx;
    const int itermax = *iter_p;

    // ---- init ----
    if (tid == 0) {
        asm volatile("mbarrier.init.shared.b64 [%0], %1;" :: "r"(smem_u32(&s->mbar[0])), "r"(CN) : "memory");
        asm volatile("mbarrier.init.shared.b64 [%0], %1;" :: "r"(smem_u32(&s->mbar[1])), "r"(CN) : "memory");
    }
    for (int i = tid; i < RPAD * NPAD; i += NTH) {
        int r = i >> 8, c = i & 255;
        bool ok = (r < RPC) && (c < NXg);
        s->kin [r][c] = ok ? kin [(row0 + r) * NXg + c] : 0.f;
        s->vint[r][c] = ok ? vint[(row0 + r) * NXg + c] : 0.f;
    }
    for (int c = tid; c < NPAD; c += NTH) {
        float a = (c < NXg) ? wfy0[c * 2 + 0] : 0.f;
        float b = (c < NXg) ? wfy0[c * 2 + 1] : 0.f;
        s->wbuf[0][0][c] = a;   s->wbuf[0][1][c] = b;
        s->wbuf[1][0][c] = 0.f; s->wbuf[1][1][c] = 0.f;
        s->fball[0][0][c] = 0.f; s->fball[0][1][c] = 0.f;
        s->fball[1][0][c] = 0.f; s->fball[1][1][c] = 0.f;
        s->uho[c] = (c < NXg) ? uho[c] : 0.f;
    }
    __syncthreads();
    CLUSTER_SYNC();   // mbar init + zero padding visible cluster-wide

    const int m = lane & 7;            // column-slice owner within 8-lane group
    const int g = lane >> 3;           // row group within warp
    const int row  = (wid << 2) + g;   // 0..31 (30,31 padded-zero rows)
    const int gi   = row0 + row;
    const bool active = row < RPC;
    const int c1 = lane * 4;           // for warp-wide dots (scalar phase / epilogue)
    const int c2 = 128 + lane * 4;

    // hoisted remote scatter addresses (per parity, target rank = m)
    uint32_t ra0[2], ra1[2];
    #pragma unroll
    for (int p = 0; p < 2; ++p) {
        ra0[p] = mapa_u32(smem_u32(&s->fball[p][0][gi]), m);
        ra1[p] = mapa_u32(smem_u32(&s->fball[p][1][gi]), m);
    }

    // ---- K,V matrix slices: iteration-invariant -> persistent registers ----
    ull KR[16], VR[16];
    {
        const float* kr = s->kin[row];
        const float* vr = s->vint[row];
        #pragma unroll
        for (int j = 0; j < 8; ++j) {
            int c = m * 4 + j * 32;
            ulonglong2 tk = *(const ulonglong2*)(kr + c);
            ulonglong2 tv = *(const ulonglong2*)(vr + c);
            KR[2*j] = tk.x; KR[2*j+1] = tk.y;
            VR[2*j] = tv.x; VR[2*j+1] = tv.y;
        }
    }

    for (int it = 0; it < itermax; ++it) {
        const int cur = it & 1, nx = cur ^ 1;
        const float* w0 = s->wbuf[cur][0];
        const float* w1 = s->wbuf[cur][1];

        // ---- RHS vectors in registers (same columns for all groups) ----
        ull A[16], B[16];
        #pragma unroll
        for (int j = 0; j < 8; ++j) {
            int c = m * 4 + j * 32;
            ulonglong2 ta = *(const ulonglong2*)(w0 + c);
            ulonglong2 tb = *(const ulonglong2*)(w1 + c);
            A[2*j] = ta.x; A[2*j+1] = ta.y;
            B[2*j] = tb.x; B[2*j+1] = tb.y;
        }

        // ---- matvec: row per 8-lane group; K,V from registers, zero SMEM ----
        ull kw0 = 0, kw1 = 0, v00 = 0, v01 = 0, v11 = 0;
        #pragma unroll
        for (int j = 0; j < 16; ++j) {
            ull a = A[j], b = B[j];
            kw0 = fma2(KR[j], a, kw0);
            kw1 = fma2(KR[j], b, kw1);
            v00 = fma2(VR[j], mul2(a, a), v00);
            v01 = fma2(VR[j], mul2(a, b), v01);
            v11 = fma2(VR[j], mul2(b, b), v11);
        }
        float skw0 = gred(hadd2(kw0));
        float skw1 = gred(hadd2(kw1));
        float sv00 = gred(hadd2(v00));
        float sv01 = gred(hadd2(v01));
        float sv11 = gred(hadd2(v11));

        // all 8 lanes of the group redundantly finish the row; lane m -> rank m
        {
            float w0i = w0[gi], w1i = w1[gi], uh = s->uho[gi];
            float ud  = delx * (sv00 + sv11);
            float hw0 = skw0 - delx * (w0i * sv00 + w1i * sv01) + (ud + uh) * w0i;
            float hw1 = skw1 - delx * (w0i * sv01 + w1i * sv11) + (ud + uh) * w1i;
            float fb0 = w0i - pfac * hw0;
            float fb1 = w1i - pfac * hw1;
            if (active) {
                if (m == 0) s->udirs[row] = ud;
                st_remote_f32(ra0[cur], fb0);
                st_remote_f32(ra1[cur], fb1);
            }
        }
        __syncthreads();                                  // barA: all scatters issued
        if (tid < CN) mbar_arrive_remote(smem_u32(&s->mbar[cur]), tid);

        // ---- pre-wait: local-only scalars (W2,V2,EH) + preload local halves ----
        float4 L0, L1;   // preloaded local operand for wid 3 (w0), 4 (w0), 5 (w1)
        if (wid == 3 || wid == 4) { L0 = *(const float4*)(w0 + c1); L1 = *(const float4*)(w0 + c2); }
        else if (wid == 5)        { L0 = *(const float4*)(w1 + c1); L1 = *(const float4*)(w1 + c2); }
        if (wid == 6) {          // W2 = w0.w0
            float4 X0 = *(const float4*)(w0 + c1), X1 = *(const float4*)(w0 + c2);
            float v = wred(dot8f(X0, X1, X0, X1));
            if (lane == 0) s->scal[5] = v;
        } else if (wid == 7) {   // V2 = w1.w1  and EH = sum (w0^2+w1^2)*uho
            float4 X0 = *(const float4*)(w1 + c1), X1 = *(const float4*)(w1 + c2);
            float v = wred(dot8f(X0, X1, X0, X1));
            float4 P0 = *(const float4*)(w0 + c1), P1 = *(const float4*)(w0 + c2);
            float4 U0 = *(const float4*)(s->uho + c1), U1 = *(const float4*)(s->uho + c2);
            float e = (P0.x*P0.x + X0.x*X0.x) * U0.x;
            e = fmaf(P0.y*P0.y + X0.y*X0.y, U0.y, e);
            e = fmaf(P0.z*P0.z + X0.z*X0.z, U0.z, e);
            e = fmaf(P0.w*P0.w + X0.w*X0.w, U0.w, e);
            e = fmaf(P1.x*P1.x + X1.x*X1.x, U1.x, e);
            e = fmaf(P1.y*P1.y + X1.y*X1.y, U1.y, e);
            e = fmaf(P1.z*P1.z + X1.z*X1.z, U1.z, e);
            e = fmaf(P1.w*P1.w + X1.w*X1.w, U1.w, e);
            e = wred(e);
            if (lane == 0) { s->scal[6] = v; s->scal[8] = e; }
        }

        mbar_wait_parity(smem_u32(&s->mbar[cur]), (uint32_t)((it >> 1) & 1));

        // ---- post-wait: 6 remote-dependent scalars, one warp each ----
        if (wid < 6) {
            const float* f0a = s->fball[cur][0];
            const float* f1a = s->fball[cur][1];
            float v;
            if (wid == 0) {        // S0 = fb0.fb0
                float4 X0 = *(const float4*)(f0a + c1), X1 = *(const float4*)(f0a + c2);
                v = dot8f(X0, X1, X0, X1);
            } else if (wid == 1) { // S1 = fb1.fb1
                float4 X0 = *(const float4*)(f1a + c1), X1 = *(const float4*)(f1a + c2);
                v = dot8f(X0, X1, X0, X1);
            } else if (wid == 2) { // Xs = fb0.fb1
                float4 X0 = *(const float4*)(f0a + c1), X1 = *(const float4*)(f0a + c2);
                float4 Y0 = *(const float4*)(f1a + c1), Y1 = *(const float4*)(f1a + c2);
                v = dot8f(X0, X1, Y0, Y1);
            } else if (wid == 3) { // Ys = w0.fb1  (L = w0 preloaded)
                float4 Y0 = *(const float4*)(f1a + c1), Y1 = *(const float4*)(f1a + c2);
                v = dot8f(L0, L1, Y0, Y1);
            } else if (wid == 4) { // Zs = fb0.w0  (L = w0 preloaded)
                float4 Y0 = *(const float4*)(f0a + c1), Y1 = *(const float4*)(f0a + c2);
                v = dot8f(L0, L1, Y0, Y1);
            } else {               // Us = w1.fb1  (L = w1 preloaded)
                float4 Y0 = *(const float4*)(f1a + c1), Y1 = *(const float4*)(f1a + c2);
                v = dot8f(L0, L1, Y0, Y1);
            }
            v = wred(v);
            if (lane == 0) {
                int idx = (wid < 5) ? wid : 7;   // S0,S1,Xs,Ys,Zs -> 0..4 ; Us -> 7
                s->scal[idx] = v;
            }
        }
        __syncthreads();                                  // barB: scalars ready

        // ---- update: every element thread, closed-form chain redundant ----
        if (tid < NXg) {
            float S0 = s->scal[0], S1 = s->scal[1], Xs = s->scal[2];
            float Ys = s->scal[3], Zs = s->scal[4], W2 = s->scal[5];
            float inv0 = rsqrtf(S0 * delx);
            float inv1 = rsqrtf(S1 * delx);
            float dGS  = FFACf * inv0 * inv1 * Xs + OMFf * inv1 * Ys;
            float sn0  = 0.16f * rdelx + 0.48f * inv0 * Zs + 0.36f * W2;
            float T1   = rdelx - dGS * dGS * delx * (2.f - delx * sn0);
            float invT1d = __fdividef(1.f, T1 * delx);
            float a0 = FFACf * inv0;
            float b1 = FFACf * invT1d * inv1;
            float cc = FFACf * invT1d * dGS * delx;
            float fb0 = s->fball[cur][0][tid];
            float fb1 = s->fball[cur][1][tid];
            float n0 = a0 * fb0 + OMFf * w0[tid];
            float n1 = b1 * fb1 - cc * n0 + OMFf * w1[tid];
            s->wbuf[nx][0][tid] = n0;
            s->wbuf[nx][1][tid] = n1;
        }
        __syncthreads();                                  // barC: wbuf[nx] ready
    }

    // ---- final energies: ekin = new.K.new, epot = new.Umf.new ----
    {
        const int fin = itermax & 1, oldp = fin ^ 1;
        const float* wo0 = s->wbuf[oldp][0]; const float* wo1 = s->wbuf[oldp][1];
        const float* nv0 = s->wbuf[fin][0];  const float* nv1 = s->wbuf[fin][1];
        ull Ao[4], Bo[4], N0[4], N1[4], P0[4], P1[4], Q0[4], Q1[4];
        ld2x2(wo0, c1, c2, Ao);
        ld2x2(wo1, c1, c2, Bo);
        ld2x2(nv0, c1, c2, N0);
        ld2x2(nv1, c1, c2, N1);
        #pragma unroll
        for (int i = 0; i < 4; ++i) {
            P0[i] = mul2(Ao[i], N0[i]);
            P1[i] = mul2(Bo[i], N0[i]);
            Q0[i] = mul2(Ao[i], N1[i]);
            Q1[i] = mul2(Bo[i], N1[i]);
        }
        float pek = 0.f, pep = 0.f;
        for (int r = wid; r < RPC; r += NW) {
            ull K[4], V[4];
            ld2x2(s->kin[r],  c1, c2, K);
            ld2x2(s->vint[r], c1, c2, V);
            float kn0 = dot4p(K, N0), kn1 = dot4p(K, N1);
            float q00 = dot4p(V, P0), q10 = dot4p(V, P1);
            float q01 = dot4p(V, Q0), q11 = dot4p(V, Q1);
            kn0 = wred(kn0); kn1 = wred(kn1);
            q00 = wred(q00); q10 = wred(q10);
            q01 = wred(q01); q11 = wred(q11);
            if (lane == 0) {
                int gr = row0 + r;
                float n0i = nv0[gr], n1i = nv1[gr];
                float w0o = wo0[gr], w1o = wo1[gr];
                float diag = s->udirs[r] + s->uho[gr];
                float um0 = -delx * (w0o * q00 + w1o * q10) + diag * n0i;
                float um1 = -delx * (w0o * q01 + w1o * q11) + diag * n1i;
                pek += n0i * kn0 + n1i * kn1;
                pep += n0i * um0 + n1i * um1;
            }
        }
        if (lane == 0) { s->wred2[wid][0] = pek; s->wred2[wid][1] = pep; }
        __syncthreads();
        if (tid < 2) {
            float v = 0.f;
            #pragma unroll
            for (int w = 0; w < NW; ++w) v += s->wred2[w][tid];
            uint32_t la = smem_u32(&s->redF[rank][tid]);
            #pragma unroll
            for (int tr = 0; tr < CN; ++tr) st_cluster_f32(la, tr, v);
        }
        CLUSTER_SYNC();
        if (rank == 0 && tid == 0) {
            float EK = 0.f, EP = 0.f;
            for (int rr = 0; rr < CN; ++rr) { EK += s->redF[rr][0]; EP += s->redF[rr][1]; }
            // last-iteration scalars are replicated in every CTA's s->scal
            float Zs = s->scal[4], W2 = s->scal[5], V2 = s->scal[6];
            float Us = s->scal[7], EH = s->scal[8];
            float esum = ((W2 - Zs) + (V2 - Us)) / pfac * delx;
            float eho  = EH * delx * 0.5f;
            float ekin = EK * delx;
            float epot = EP * delx;
            float enerhfp = (esum + ekin) * 0.5f + eho;
            float epot0   = epot - 2.f * eho;
            float enerhf  = esum - epot0 * 0.5f;
            out[0] = enerhf; out[1] = enerhfp; out[2] = ekin;
            out[3] = eho;    out[4] = epot0;   out[5] = esum;
        }
    }
}

extern "C" void kernel_launch(void* const* d_in, const int* in_sizes, int n_in,
                              void* d_out, int out_size) {
    (void)in_sizes; (void)n_in; (void)out_size;
    cudaFuncSetAttribute(hf_kernel, cudaFuncAttributeMaxDynamicSharedMemorySize,
                         (int)sizeof(Smem));
    hf_kernel<<<CN, NTH, sizeof(Smem)>>>(
        (const float*)d_in[0],   // wfy0 (240,2)
        (const float*)d_in[1],   // kin_mat (240,240)
        (const float*)d_in[2],   // Vint (240,240)
        (const float*)d_in[3],   // U_HO (240)
        (const float*)d_in[4],   // delx
        (const float*)d_in[5],   // pfac
        (const int*)d_in[6],     // itermax
        (float*)d_out);          // 6 outputs
}

// round 13
// speedup vs baseline: 1.3808x; 1.0399x over previous
#include <cuda_runtime.h>
#include <cstdint>

#define NXg   240
#define NPAD  256
#define CN    8      // cluster size (CTAs)
#define RPC   30     // rows per CTA
#define RPAD  32     // padded row count (rows 30,31 zero)
#define NTH   256    // 8 warps
#define NW    8
#define FFACf 0.4f
#define OMFf  0.6f

typedef unsigned long long ull;

struct __align__(16) Smem {
    alignas(16) ull   mbar[2];            // ping-pong cluster barriers (count=8)
    alignas(16) float scal[12];           // 9 global scalars (per-CTA replicated)
    alignas(16) float udirs[32];
    alignas(16) float wred2[NW][2];
    alignas(16) float redF[CN][2];        // final-energy cluster slots
    alignas(16) float uho [NPAD];
    alignas(16) float wbuf [2][2][NPAD];  // ping-pong wavefunctions (local)
    alignas(16) ull   fball[2][NPAD];     // ping-pong broadcast (fb0,fb1) pairs (DSMEM-filled)
    alignas(16) float kin [RPAD][NPAD];
    alignas(16) float vint[RPAD][NPAD];
};

__device__ __forceinline__ uint32_t smem_u32(const void* p) {
    return (uint32_t)__cvta_generic_to_shared(p);
}
__device__ __forceinline__ uint32_t mapa_u32(uint32_t laddr, int rank) {
    uint32_t r;
    asm("mapa.shared::cluster.u32 %0, %1, %2;" : "=r"(r) : "r"(laddr), "r"(rank));
    return r;
}
__device__ __forceinline__ void st_remote_f32(uint32_t raddr, float v) {
    asm volatile("st.shared::cluster.u32 [%0], %1;" :: "r"(raddr), "r"(__float_as_uint(v)) : "memory");
}
__device__ __forceinline__ void st_remote_b64(uint32_t raddr, ull v) {
    asm volatile("st.shared::cluster.b64 [%0], %1;" :: "r"(raddr), "l"(v) : "memory");
}
__device__ __forceinline__ void st_cluster_f32(uint32_t laddr, int rank, float v) {
    st_remote_f32(mapa_u32(laddr, rank), v);
}
__device__ __forceinline__ void mbar_arrive_remote(uint32_t laddr, int rank) {
    asm volatile("{\n\t.reg .b32 ra;\n\t"
        "mapa.shared::cluster.u32 ra, %0, %1;\n\t"
        "mbarrier.arrive.release.cluster.shared::cluster.b64 _, [ra];\n\t}"
        :: "r"(laddr), "r"(rank) : "memory");
}
__device__ __forceinline__ void mbar_wait_parity(uint32_t addr, uint32_t parity) {
    uint32_t done;
    asm volatile("{\n\t.reg .pred p;\n\t"
        "mbarrier.try_wait.parity.acquire.cluster.shared::cta.b64 p, [%1], %2;\n\t"
        "selp.b32 %0, 1, 0, p;\n\t}"
        : "=r"(done) : "r"(addr), "r"(parity) : "memory");
    if (!done) {
        asm volatile("{\n\t.reg .pred P1;\n\t"
            "W_%=:\n\t"
            "mbarrier.try_wait.parity.acquire.cluster.shared::cta.b64 P1, [%0], %1, 0x989680;\n\t"
            "@P1 bra.uni D_%=;\n\t"
            "bra.uni W_%=;\n\t"
            "D_%=:\n\t}"
            :: "r"(addr), "r"(parity) : "memory");
    }
}
#define CLUSTER_SYNC() do { \
    asm volatile("barrier.cluster.arrive.aligned;" ::: "memory"); \
    asm volatile("barrier.cluster.wait.aligned;"   ::: "memory"); \
} while (0)

__device__ __forceinline__ float wred(float v) {     // full-warp sum
    v += __shfl_xor_sync(0xFFFFFFFFu, v, 16);
    v += __shfl_xor_sync(0xFFFFFFFFu, v, 8);
    v += __shfl_xor_sync(0xFFFFFFFFu, v, 4);
    v += __shfl_xor_sync(0xFFFFFFFFu, v, 2);
    v += __shfl_xor_sync(0xFFFFFFFFu, v, 1);
    return v;
}
__device__ __forceinline__ float gred(float v) {     // 8-lane group sum (all lanes get it)
    v += __shfl_xor_sync(0xFFFFFFFFu, v, 4);
    v += __shfl_xor_sync(0xFFFFFFFFu, v, 2);
    v += __shfl_xor_sync(0xFFFFFFFFu, v, 1);
    return v;
}

// ---- packed f32x2 helpers (FFMA2, PTX-only) ----
__device__ __forceinline__ ull mul2(ull a, ull b) {
    ull d; asm("mul.rn.f32x2 %0, %1, %2;" : "=l"(d) : "l"(a), "l"(b)); return d;
}
__device__ __forceinline__ ull fma2(ull a, ull b, ull c) {
    ull d; asm("fma.rn.f32x2 %0, %1, %2, %3;" : "=l"(d) : "l"(a), "l"(b), "l"(c)); return d;
}
__device__ __forceinline__ float hadd2(ull a) {
    uint32_t lo, hi;
    asm("mov.b64 {%0, %1}, %2;" : "=r"(lo), "=r"(hi) : "l"(a));
    return __uint_as_float(lo) + __uint_as_float(hi);
}
__device__ __forceinline__ ull pack2(float lo, float hi) {
    ull d; asm("mov.b64 %0, {%1, %2};" : "=l"(d) : "r"(__float_as_uint(lo)), "r"(__float_as_uint(hi)));
    return d;
}
__device__ __forceinline__ void unpack2(ull a, float& lo, float& hi) {
    uint32_t l, h;
    asm("mov.b64 {%0, %1}, %2;" : "=r"(l), "=r"(h) : "l"(a));
    lo = __uint_as_float(l); hi = __uint_as_float(h);
}
__device__ __forceinline__ ull swap2(ull a) {
    uint32_t l, h;
    asm("mov.b64 {%0, %1}, %2;" : "=r"(l), "=r"(h) : "l"(a));
    ull d; asm("mov.b64 %0, {%1, %2};" : "=l"(d) : "r"(h), "r"(l));
    return d;
}
__device__ __forceinline__ void ld2x2(const float* p, int c1, int c2, ull* o) {
    ulonglong2 t0 = *reinterpret_cast<const ulonglong2*>(p + c1);
    ulonglong2 t1 = *reinterpret_cast<const ulonglong2*>(p + c2);
    o[0] = t0.x; o[1] = t0.y; o[2] = t1.x; o[3] = t1.y;
}
__device__ __forceinline__ float dot4p(const ull* k, const ull* x) {
    ull acc = mul2(k[0], x[0]);
    acc = fma2(k[1], x[1], acc);
    acc = fma2(k[2], x[2], acc);
    acc = fma2(k[3], x[3], acc);
    return hadd2(acc);
}
__device__ __forceinline__ float dot8f(float4 a0, float4 a1, float4 b0, float4 b1) {
    float s0 = a0.x * b0.x, s1 = a0.y * b0.y;
    s0 = fmaf(a0.z, b0.z, s0); s1 = fmaf(a0.w, b0.w, s1);
    s0 = fmaf(a1.x, b1.x, s0); s1 = fmaf(a1.y, b1.y, s1);
    s0 = fmaf(a1.z, b1.z, s0); s1 = fmaf(a1.w, b1.w, s1);
    return s0 + s1;
}
// load 4 (fb0,fb1) pairs at element base c (c multiple of 4)
__device__ __forceinline__ void ldp4(const ull* fbp, int c, ull* o) {
    ulonglong2 t0 = *reinterpret_cast<const ulonglong2*>(fbp + c);
    ulonglong2 t1 = *reinterpret_cast<const ulonglong2*>(fbp + c + 2);
    o[0] = t0.x; o[1] = t0.y; o[2] = t1.x; o[3] = t1.y;
}

__global__ void __launch_bounds__(NTH, 1) __cluster_dims__(CN, 1, 1)
hf_kernel(const float* __restrict__ wfy0, const float* __restrict__ kin,
          const float* __restrict__ vint, const float* __restrict__ uho,
          const float* __restrict__ delx_p, const float* __restrict__ pfac_p,
          const int* __restrict__ iter_p, float* __restrict__ out)
{
    extern __shared__ char smraw[];
    Smem* s = reinterpret_cast<Smem*>(smraw);
    const int tid  = threadIdx.x;
    const int wid  = tid >> 5;
    const int lane = tid & 31;
    uint32_t rank;
    asm("mov.u32 %0, %%cluster_ctarank;" : "=r"(rank));
    const int row0 = (int)rank * RPC;
    const float delx = *delx_p;
    const float pfac = *pfac_p;
    const float rdelx = 1.f / delx;
    const int itermax = *iter_p;

    // ---- init ----
    if (tid == 0) {
        asm volatile("mbarrier.init.shared.b64 [%0], %1;" :: "r"(smem_u32(&s->mbar[0])), "r"(CN) : "memory");
        asm volatile("mbarrier.init.shared.b64 [%0], %1;" :: "r"(smem_u32(&s->mbar[1])), "r"(CN) : "memory");
    }
    for (int i = tid; i < RPAD * NPAD; i += NTH) {
        int r = i >> 8, c = i & 255;
        bool ok = (r < RPC) && (c < NXg);
        s->kin [r][c] = ok ? kin [(row0 + r) * NXg + c] : 0.f;
        s->vint[r][c] = ok ? vint[(row0 + r) * NXg + c] : 0.f;
    }
    for (int c = tid; c < NPAD; c += NTH) {
        float a = (c < NXg) ? wfy0[c * 2 + 0] : 0.f;
        float b = (c < NXg) ? wfy0[c * 2 + 1] : 0.f;
        s->wbuf[0][0][c] = a;   s->wbuf[0][1][c] = b;
        s->wbuf[1][0][c] = 0.f; s->wbuf[1][1][c] = 0.f;
        s->fball[0][c] = 0ull;  s->fball[1][c] = 0ull;
        s->uho[c] = (c < NXg) ? uho[c] : 0.f;
    }
    __syncthreads();
    CLUSTER_SYNC();   // mbar init + zero padding visible cluster-wide

    const int m = lane & 7;            // column-slice owner within 8-lane group
    const int g = lane >> 3;           // row group within warp
    const int row  = (wid << 2) + g;   // 0..31 (30,31 padded-zero rows)
    const int gi   = row0 + row;
    const bool active = row < RPC;
    const int c1 = lane * 4;           // for warp-wide dots (scalar phase / epilogue)
    const int c2 = 128 + lane * 4;

    // hoisted remote scatter addresses (per parity, target rank = m)
    uint32_t ra[2];
    #pragma unroll
    for (int p = 0; p < 2; ++p)
        ra[p] = mapa_u32(smem_u32(&s->fball[p][gi]), m);

    // ---- K,V matrix slices: iteration-invariant -> persistent registers ----
    ull KR[16], VR[16];
    {
        const float* kr = s->kin[row];
        const float* vr = s->vint[row];
        #pragma unroll
        for (int j = 0; j < 8; ++j) {
            int c = m * 4 + j * 32;
            ulonglong2 tk = *(const ulonglong2*)(kr + c);
            ulonglong2 tv = *(const ulonglong2*)(vr + c);
            KR[2*j] = tk.x; KR[2*j+1] = tk.y;
            VR[2*j] = tv.x; VR[2*j+1] = tv.y;
        }
    }

    for (int it = 0; it < itermax; ++it) {
        const int cur = it & 1, nx = cur ^ 1;
        const float* w0 = s->wbuf[cur][0];
        const float* w1 = s->wbuf[cur][1];

        // ---- RHS vectors in registers + hoisted epilogue element loads ----
        ull A[16], B[16];
        #pragma unroll
        for (int j = 0; j < 8; ++j) {
            int c = m * 4 + j * 32;
            ulonglong2 ta = *(const ulonglong2*)(w0 + c);
            ulonglong2 tb = *(const ulonglong2*)(w1 + c);
            A[2*j] = ta.x; A[2*j+1] = ta.y;
            B[2*j] = tb.x; B[2*j+1] = tb.y;
        }
        float w0i = w0[gi], w1i = w1[gi], uh = s->uho[gi];   // hoisted (broadcast LDS)

        // ---- matvec: row per 8-lane group; K,V from registers, zero SMEM ----
        ull kw0 = 0, kw1 = 0, v00 = 0, v01 = 0, v11 = 0;
        #pragma unroll
        for (int j = 0; j < 16; ++j) {
            ull a = A[j], b = B[j];
            kw0 = fma2(KR[j], a, kw0);
            kw1 = fma2(KR[j], b, kw1);
            v00 = fma2(VR[j], mul2(a, a), v00);
            v01 = fma2(VR[j], mul2(a, b), v01);
            v11 = fma2(VR[j], mul2(b, b), v11);
        }
        float skw0 = gred(hadd2(kw0));
        float skw1 = gred(hadd2(kw1));
        float sv00 = gred(hadd2(v00));
        float sv01 = gred(hadd2(v01));
        float sv11 = gred(hadd2(v11));

        // all 8 lanes of the group redundantly finish the row; lane m -> rank m
        {
            float ud  = delx * (sv00 + sv11);
            float hw0 = skw0 - delx * (w0i * sv00 + w1i * sv01) + (ud + uh) * w0i;
            float hw1 = skw1 - delx * (w0i * sv01 + w1i * sv11) + (ud + uh) * w1i;
            float fb0 = w0i - pfac * hw0;
            float fb1 = w1i - pfac * hw1;
            if (active) {
                if (m == 0) s->udirs[row] = ud;
                st_remote_b64(ra[cur], pack2(fb0, fb1));
            }
        }
        __syncthreads();                                  // barA: all scatters issued
        if (tid < CN) mbar_arrive_remote(smem_u32(&s->mbar[cur]), tid);

        // ---- pre-wait: local-only scalars (W2,V2,EH) + dup-pack preloads ----
        ull D0[8];   // dup-packed local operand for wid 2 (w0 dups), wid 3 (w1 dups)
        if (wid == 2 || wid == 3) {
            const float* wv = (wid == 2) ? w0 : w1;
            float4 L0 = *(const float4*)(wv + c1), L1 = *(const float4*)(wv + c2);
            D0[0] = pack2(L0.x, L0.x); D0[1] = pack2(L0.y, L0.y);
            D0[2] = pack2(L0.z, L0.z); D0[3] = pack2(L0.w, L0.w);
            D0[4] = pack2(L1.x, L1.x); D0[5] = pack2(L1.y, L1.y);
            D0[6] = pack2(L1.z, L1.z); D0[7] = pack2(L1.w, L1.w);
        }
        if (wid == 6) {          // W2 = w0.w0
            float4 X0 = *(const float4*)(w0 + c1), X1 = *(const float4*)(w0 + c2);
            float v = wred(dot8f(X0, X1, X0, X1));
            if (lane == 0) s->scal[5] = v;
        } else if (wid == 7) {   // V2 = w1.w1  and EH = sum (w0^2+w1^2)*uho
            float4 X0 = *(const float4*)(w1 + c1), X1 = *(const float4*)(w1 + c2);
            float v = wred(dot8f(X0, X1, X0, X1));
            float4 P0 = *(const float4*)(w0 + c1), P1 = *(const float4*)(w0 + c2);
            float4 U0 = *(const float4*)(s->uho + c1), U1 = *(const float4*)(s->uho + c2);
            float e = (P0.x*P0.x + X0.x*X0.x) * U0.x;
            e = fmaf(P0.y*P0.y + X0.y*X0.y, U0.y, e);
            e = fmaf(P0.z*P0.z + X0.z*X0.z, U0.z, e);
            e = fmaf(P0.w*P0.w + X0.w*X0.w, U0.w, e);
            e = fmaf(P1.x*P1.x + X1.x*X1.x, U1.x, e);
            e = fmaf(P1.y*P1.y + X1.y*X1.y, U1.y, e);
            e = fmaf(P1.z*P1.z + X1.z*X1.z, U1.z, e);
            e = fmaf(P1.w*P1.w + X1.w*X1.w, U1.w, e);
            e = wred(e);
            if (lane == 0) { s->scal[6] = v; s->scal[8] = e; }
        }

        mbar_wait_parity(smem_u32(&s->mbar[cur]), (uint32_t)((it >> 1) & 1));

        // ---- post-wait: packed-pair dots, 4 warps cover 6 scalars ----
        if (wid < 4) {
            const ull* fbp = s->fball[cur];
            ull P[8];
            ldp4(fbp, c1, P);
            ldp4(fbp, c2, P + 4);
            if (wid == 0) {        // (S0, S1) = sum p*p
                ull acc = mul2(P[0], P[0]);
                #pragma unroll
                for (int j = 1; j < 8; ++j) acc = fma2(P[j], P[j], acc);
                float sa, sb; unpack2(acc, sa, sb);
                sa = wred(sa); sb = wred(sb);
                if (lane == 0) { s->scal[0] = sa; s->scal[1] = sb; }
            } else if (wid == 1) { // Xs = sum fb0*fb1 (lo half of p*swap(p))
                ull acc = mul2(P[0], swap2(P[0]));
                #pragma unroll
                for (int j = 1; j < 8; ++j) acc = fma2(P[j], swap2(P[j]), acc);
                float sa, sb; unpack2(acc, sa, sb);
                sa = wred(sa);
                if (lane == 0) s->scal[2] = sa;
            } else if (wid == 2) { // (Zs, Ys) = sum dup(w0)*p
                ull acc = mul2(D0[0], P[0]);
                #pragma unroll
                for (int j = 1; j < 8; ++j) acc = fma2(D0[j], P[j], acc);
                float sa, sb; unpack2(acc, sa, sb);
                sa = wred(sa); sb = wred(sb);
                if (lane == 0) { s->scal[4] = sa; s->scal[3] = sb; }
            } else {               // Us = hi of sum dup(w1)*p
                ull acc = mul2(D0[0], P[0]);
                #pragma unroll
                for (int j = 1; j < 8; ++j) acc = fma2(D0[j], P[j], acc);
                float sa, sb; unpack2(acc, sa, sb);
                sb = wred(sb);
                if (lane == 0) s->scal[7] = sb;
            }
        }
        __syncthreads();                                  // barB: scalars ready

        // ---- update: every element thread, closed-form chain redundant ----
        if (tid < NXg) {
            float S0 = s->scal[0], S1 = s->scal[1], Xs = s->scal[2];
            float Ys = s->scal[3], Zs = s->scal[4], W2 = s->scal[5];
            float inv0 = rsqrtf(S0 * delx);
            float inv1 = rsqrtf(S1 * delx);
            float dGS  = FFACf * inv0 * inv1 * Xs + OMFf * inv1 * Ys;
            float sn0  = 0.16f * rdelx + 0.48f * inv0 * Zs + 0.36f * W2;
            float T1   = rdelx - dGS * dGS * delx * (2.f - delx * sn0);
            float invT1d = __fdividef(1.f, T1 * delx);
            float a0 = FFACf * inv0;
            float b1 = FFACf * invT1d * inv1;
            float cc = FFACf * invT1d * dGS * delx;
            float fb0, fb1;
            unpack2(s->fball[cur][tid], fb0, fb1);
            float n0 = a0 * fb0 + OMFf * w0[tid];
            float n1 = b1 * fb1 - cc * n0 + OMFf * w1[tid];
            s->wbuf[nx][0][tid] = n0;
            s->wbuf[nx][1][tid] = n1;
        }
        __syncthreads();                                  // barC: wbuf[nx] ready
    }

    // ---- final energies: ekin = new.K.new, epot = new.Umf.new ----
    {
        const int fin = itermax & 1, oldp = fin ^ 1;
        const float* wo0 = s->wbuf[oldp][0]; const float* wo1 = s->wbuf[oldp][1];
        const float* nv0 = s->wbuf[fin][0];  const float* nv1 = s->wbuf[fin][1];
        ull Ao[4], Bo[4], N0[4], N1[4], P0[4], P1[4], Q0[4], Q1[4];
        ld2x2(wo0, c1, c2, Ao);
        ld2x2(wo1, c1, c2, Bo);
        ld2x2(nv0, c1, c2, N0);
        ld2x2(nv1, c1, c2, N1);
        #pragma unroll
        for (int i = 0; i < 4; ++i) {
            P0[i] = mul2(Ao[i], N0[i]);
            P1[i] = mul2(Bo[i], N0[i]);
            Q0[i] = mul2(Ao[i], N1[i]);
            Q1[i] = mul2(Bo[i], N1[i]);
        }
        float pek = 0.f, pep = 0.f;
        for (int r = wid; r < RPC; r += NW) {
            ull K[4], V[4];
            ld2x2(s->kin[r],  c1, c2, K);
            ld2x2(s->vint[r], c1, c2, V);
            float kn0 = dot4p(K, N0), kn1 = dot4p(K, N1);
            float q00 = dot4p(V, P0), q10 = dot4p(V, P1);
            float q01 = dot4p(V, Q0), q11 = dot4p(V, Q1);
            kn0 = wred(kn0); kn1 = wred(kn1);
            q00 = wred(q00); q10 = wred(q10);
            q01 = wred(q01); q11 = wred(q11);
            if (lane == 0) {
                int gr = row0 + r;
                float n0i = nv0[gr], n1i = nv1[gr];
                float w0o = wo0[gr], w1o = wo1[gr];
                float diag = s->udirs[r] + s->uho[gr];
                float um0 = -delx * (w0o * q00 + w1o * q10) + diag * n0i;
                float um1 = -delx * (w0o * q01 + w1o * q11) + diag * n1i;
                pek += n0i * kn0 + n1i * kn1;
                pep += n0i * um0 + n1i * um1;
            }
        }
        if (lane == 0) { s->wred2[wid][0] = pek; s->wred2[wid][1] = pep; }
        __syncthreads();
        if (tid < 2) {
            float v = 0.f;
            #pragma unroll
            for (int w = 0; w < NW; ++w) v += s->wred2[w][tid];
            uint32_t la = smem_u32(&s->redF[rank][tid]);
            #pragma unroll
            for (int tr = 0; tr < CN; ++tr) st_cluster_f32(la, tr, v);
        }
        CLUSTER_SYNC();
        if (rank == 0 && tid == 0) {
            float EK = 0.f, EP = 0.f;
            for (int rr = 0; rr < CN; ++rr) { EK += s->redF[rr][0]; EP += s->redF[rr][1]; }
            // last-iteration scalars are replicated in every CTA's s->scal
            float Zs = s->scal[4], W2 = s->scal[5], V2 = s->scal[6];
            float Us = s->scal[7], EH = s->scal[8];
            float esum = ((W2 - Zs) + (V2 - Us)) / pfac * delx;
            float eho  = EH * delx * 0.5f;
            float ekin = EK * delx;
            float epot = EP * delx;
            float enerhfp = (esum + ekin) * 0.5f + eho;
            float epot0   = epot - 2.f * eho;
            float enerhf  = esum - epot0 * 0.5f;
            out[0] = enerhf; out[1] = enerhfp; out[2] = ekin;
            out[3] = eho;    out[4] = epot0;   out[5] = esum;
        }
    }
}

extern "C" void kernel_launch(void* const* d_in, const int* in_sizes, int n_in,
                              void* d_out, int out_size) {
    (void)in_sizes; (void)n_in; (void)out_size;
    cudaFuncSetAttribute(hf_kernel, cudaFuncAttributeMaxDynamicSharedMemorySize,
                         (int)sizeof(Smem));
    hf_kernel<<<CN, NTH, sizeof(Smem)>>>(
        (const float*)d_in[0],   // wfy0 (240,2)
        (const float*)d_in[1],   // kin_mat (240,240)
        (const float*)d_in[2],   // Vint (240,240)
        (const float*)d_in[3],   // U_HO (240)
        (const float*)d_in[4],   // delx
        (const float*)d_in[5],   // pfac
        (const int*)d_in[6],     // itermax
        (float*)d_out);          // 6 outputs
}